// round 14
// baseline (speedup 1.0000x reference)
#include <cuda_runtime.h>
#include <cuda_fp16.h>
#include <cstdint>

// Problem constants
#define B_  2
#define L_  16384
#define C_  512
#define H_  16
#define D_  32
#define K_  7
#define SCALE_ 0.17677669529663687f   // 32^-0.5
#define MTOT (B_ * L_)                // 32768

// Scratch (device globals). Blocked fp16 layout for GEMM operands:
//   buf[kb][row][32 halves], kb = k/32, with 16B-chunk swizzle c ^= (row>>1)&3
__device__ __half g_xb [(size_t)MTOT * C_];          // x, blocked
__device__ __half g_w1b[(size_t)3 * C_ * C_];        // qkv_w, blocked (rows = N)
__device__ __half g_w2b[(size_t)C_ * C_];            // proj_w, blocked
__device__ __half g_qkv[(size_t)MTOT * 3 * C_];      // qkv, plain row-major fp16
__device__ __half g_aob[(size_t)MTOT * C_];          // attention out, blocked

// ---------------------------------------------------------------------------
// f32 row-major [Mrows][512] -> blocked swizzled fp16 [kb][m][32]
// ---------------------------------------------------------------------------
__global__ void cvt_blocked_kernel(const float* __restrict__ in,
                                   __half* __restrict__ out, int Mrows)
{
    int t  = blockIdx.x * blockDim.x + threadIdx.x;
    int kb = blockIdx.y;
    int m  = t >> 2;
    int cd = t & 3;                       // stored chunk index
    if (m >= Mrows) return;
    int c = cd ^ ((m >> 1) & 3);          // logical chunk (involution)
    const float* src = in + (size_t)m * C_ + kb * 32 + c * 8;
    float4 v0 = *(const float4*)(src + 0);
    float4 v1 = *(const float4*)(src + 4);
    __half2 h0 = __floats2half2_rn(v0.x, v0.y);
    __half2 h1 = __floats2half2_rn(v0.z, v0.w);
    __half2 h2 = __floats2half2_rn(v1.x, v1.y);
    __half2 h3 = __floats2half2_rn(v1.z, v1.w);
    uint4 u;
    u.x = *(unsigned*)&h0; u.y = *(unsigned*)&h1;
    u.z = *(unsigned*)&h2; u.w = *(unsigned*)&h3;
    *(uint4*)(out + (((size_t)kb * Mrows + m) * 32 + cd * 8)) = u;
}

// ---------------------------------------------------------------------------
// FP16 tensor-core GEMM (f32 accum), bulk-async producer/consumer pipeline:
//   C[M,N] = A[M,K] @ W[N,K]^T + bias[N]
// Block 128x256, 256 threads (8 warps), warp tile 64x64, mma.m16n8k16,
// ldmatrix.x4, 6-slot bulk+mbarrier pipeline (3 slot-pairs), software-
// pipelined fragment double-buffering, NO CTA barriers in mainloop.
// Requires M%128==0, N%256==0, K==512.
// ---------------------------------------------------------------------------
#define GBM 128
#define GBN 256
#define GBK 32
#define A_BYT (GBM * 64)              // 8192
#define B_BYT (GBN * 64)              // 16384
#define STG   (A_BYT + B_BYT)         // 24576
#define NSTG  6
#define MBAR_OFF (NSTG * STG)         // 147456
#define EMPT_OFF (MBAR_OFF + NSTG * 8)
#define SMEM_REQ (EMPT_OFF + NSTG * 8)

__device__ __forceinline__ void mma16(float* d, const unsigned* a, const unsigned* b) {
    asm volatile(
        "mma.sync.aligned.m16n8k16.row.col.f32.f16.f16.f32 "
        "{%0,%1,%2,%3},{%4,%5,%6,%7},{%8,%9},{%0,%1,%2,%3};\n"
        : "+f"(d[0]), "+f"(d[1]), "+f"(d[2]), "+f"(d[3])
        : "r"(a[0]), "r"(a[1]), "r"(a[2]), "r"(a[3]), "r"(b[0]), "r"(b[1]));
}

__device__ __forceinline__ void ldsm4(unsigned* r, uint32_t addr) {
    asm volatile(
        "ldmatrix.sync.aligned.m8n8.x4.shared.b16 {%0,%1,%2,%3}, [%4];"
        : "=r"(r[0]), "=r"(r[1]), "=r"(r[2]), "=r"(r[3]) : "r"(addr));
}

__device__ __forceinline__ void mbar_init(uint32_t a, uint32_t cnt) {
    asm volatile("mbarrier.init.shared.b64 [%0], %1;" :: "r"(a), "r"(cnt) : "memory");
}
__device__ __forceinline__ void mbar_expect(uint32_t a, uint32_t tx) {
    asm volatile("mbarrier.arrive.expect_tx.shared.b64 _, [%0], %1;"
                 :: "r"(a), "r"(tx) : "memory");
}
__device__ __forceinline__ void mbar_arrive(uint32_t a) {
    asm volatile("mbarrier.arrive.shared.b64 _, [%0];" :: "r"(a) : "memory");
}
__device__ __forceinline__ void mbar_wait(uint32_t addr, uint32_t parity) {
    asm volatile(
        "{\n\t.reg .pred P;\n"
        "W%=:\n\t"
        "mbarrier.try_wait.parity.acquire.cta.shared::cta.b64 P, [%0], %1, 0x989680;\n\t"
        "@P bra D%=;\n\t"
        "bra W%=;\n"
        "D%=:\n\t}"
        :: "r"(addr), "r"(parity) : "memory");
}
__device__ __forceinline__ void bulk_g2s(uint32_t dst, const void* src,
                                         uint32_t bytes, uint32_t mbar) {
    asm volatile(
        "cp.async.bulk.shared::cta.global.mbarrier::complete_tx::bytes "
        "[%0], [%1], %2, [%3];"
        :: "r"(dst), "l"(src), "r"(bytes), "r"(mbar) : "memory");
}

struct Frag { unsigned a[4][4]; unsigned b[8][2]; };

template<bool HOUT>
__global__ __launch_bounds__(256, 1) void gemm_f16_blk(
    const __half* __restrict__ Ab, const __half* __restrict__ Wb,
    const float* __restrict__ bias, void* __restrict__ Co,
    int M, int N)
{
    extern __shared__ char smem_raw[];
    uint32_t base;
    asm("{ .reg .u64 t; cvta.to.shared.u64 t, %1; cvt.u32.u64 %0, t; }"
        : "=r"(base) : "l"(smem_raw));

    const int tid  = threadIdx.x;
    const int lane = tid & 31;
    const int warp = tid >> 5;
    const int bm = blockIdx.y * GBM;
    const int bn = blockIdx.x * GBN;
    const int wm0 = (warp >> 2) * 64;   // 0 or 64
    const int wn0 = (warp & 3) * 64;    // 0,64,128,192
    const int NP = (C_ / GBK) / 2;      // 8 pair-rounds

    const uint32_t mbf = base + MBAR_OFF;   // full barriers
    const uint32_t mbe = base + EMPT_OFF;   // empty barriers

    if (tid == 0) {
#pragma unroll
        for (int s = 0; s < NSTG; s++) {
            mbar_init(mbf + s * 8, 1);
            mbar_init(mbe + s * 8, 8);      // one arrive per warp
        }
    }
    __syncthreads();   // only CTA barrier: mbarrier init visibility

    // Issue tile kt into slot
    auto issue = [&](int kt, int slot) {
        uint32_t bar = mbf + slot * 8;
        mbar_expect(bar, STG);
        const char* srcA = (const char*)Ab + ((size_t)kt * M + bm) * 64;
        const char* srcB = (const char*)Wb + ((size_t)kt * N + bn) * 64;
        bulk_g2s(base + slot * STG,          srcA, A_BYT, bar);
        bulk_g2s(base + slot * STG + A_BYT,  srcB, B_BYT, bar);
    };

    // Prologue: pairs 0 and 1 (tiles 0..3)
    if (tid == 0) {
        issue(0, 0); issue(1, 1);
        issue(2, 2); issue(3, 3);
    }

    float acc[4][8][4];
#pragma unroll
    for (int i = 0; i < 4; i++)
#pragma unroll
        for (int j = 0; j < 8; j++)
#pragma unroll
            for (int c = 0; c < 4; c++) acc[i][j][c] = 0.f;

    // ldmatrix lane addressing
    const int a_row = (lane & 15);
    const int a_c1  = (lane >> 4);
    const int b_row = (lane & 7) + ((lane >> 4) & 1) * 8;
    const int b_c1  = ((lane >> 3) & 1);

    auto load_frags = [&](Frag& f, uint32_t sa, int ks) {
        const uint32_t sb = sa + A_BYT;
#pragma unroll
        for (int mt = 0; mt < 4; mt++) {
            int row = wm0 + mt * 16 + a_row;
            int c = (ks * 2 + a_c1) ^ ((row >> 1) & 3);
            ldsm4(f.a[mt], sa + row * 64 + c * 16);
        }
#pragma unroll
        for (int p = 0; p < 4; p++) {
            unsigned t[4];
            int row = wn0 + p * 16 + b_row;
            int c = (ks * 2 + b_c1) ^ ((row >> 1) & 3);
            ldsm4(t, sb + row * 64 + c * 16);
            f.b[2 * p + 0][0] = t[0]; f.b[2 * p + 0][1] = t[1];
            f.b[2 * p + 1][0] = t[2]; f.b[2 * p + 1][1] = t[3];
        }
    };
    auto mma_all = [&](Frag& f) {
#pragma unroll
        for (int mt = 0; mt < 4; mt++)
#pragma unroll
            for (int nt = 0; nt < 8; nt++)
                mma16(acc[mt][nt], f.a[mt], f.b[nt]);
    };

    Frag F0, F1;

    for (int kp = 0; kp < NP; kp++) {
        const int s0 = (kp % 3) * 2;
        const uint32_t par = (kp / 3) & 1;
        mbar_wait(mbf + s0 * 8, par);
        mbar_wait(mbf + (s0 + 1) * 8, par);

        // Producer: issue pair kp+2 once its slot-pair is empty.
        if (tid == 0 && kp + 2 < NP) {
            const int np = kp + 2;
            const int ns = (np % 3) * 2;
            const uint32_t epar = 1u ^ ((uint32_t)(np / 3) & 1u);
            mbar_wait(mbe + ns * 8, epar);
            mbar_wait(mbe + (ns + 1) * 8, epar);
            issue(2 * np, ns);
            issue(2 * np + 1, ns + 1);
        }

        const uint32_t sa0 = base + s0 * STG;
        const uint32_t sa1 = sa0 + STG;

        // Software-pipelined: ldsm(step+1) overlaps mma(step)
        load_frags(F0, sa0, 0);
        load_frags(F1, sa0, 1);  mma_all(F0);
        load_frags(F0, sa1, 0);  mma_all(F1);
        load_frags(F1, sa1, 1);  mma_all(F0);
        mma_all(F1);

        if (lane == 0) {
            mbar_arrive(mbe + s0 * 8);
            mbar_arrive(mbe + (s0 + 1) * 8);
        }
    }

    // Epilogue: bias + store
    const int g  = lane >> 2;
    const int tq = lane & 3;
#pragma unroll
    for (int nt = 0; nt < 8; nt++) {
        int col = bn + wn0 + nt * 8 + tq * 2;
        float2 bb = *(const float2*)&bias[col];
#pragma unroll
        for (int mt = 0; mt < 4; mt++) {
            int row = bm + wm0 + mt * 16 + g;
            if (HOUT) {
                __half* cp = (__half*)Co;
                __half2 v0 = __floats2half2_rn(acc[mt][nt][0] + bb.x,
                                               acc[mt][nt][1] + bb.y);
                __half2 v1 = __floats2half2_rn(acc[mt][nt][2] + bb.x,
                                               acc[mt][nt][3] + bb.y);
                *(__half2*)(cp + (size_t)row * N + col) = v0;
                *(__half2*)(cp + (size_t)(row + 8) * N + col) = v1;
            } else {
                float* cp = (float*)Co;
                float2 o0, o1;
                o0.x = acc[mt][nt][0] + bb.x; o0.y = acc[mt][nt][1] + bb.y;
                o1.x = acc[mt][nt][2] + bb.x; o1.y = acc[mt][nt][3] + bb.y;
                *(float2*)(cp + (size_t)row * N + col) = o0;
                *(float2*)(cp + (size_t)(row + 8) * N + col) = o1;
            }
        }
    }
}

// ---------------------------------------------------------------------------
// Neighborhood attention, K=7, D=32. fp16 qkv in; blocked fp16 ao out.
// ---------------------------------------------------------------------------
#define TL 128

__global__ __launch_bounds__(128) void natt_kernel(
    const __half* __restrict__ qkv, const float* __restrict__ rpb,
    __half* __restrict__ aob)
{
    __shared__ float ks[134][33];
    __shared__ float vs[134][33];

    const int b  = blockIdx.z;
    const int h  = blockIdx.y;
    const int l0 = blockIdx.x * TL;
    const int tid = threadIdx.x;

    const int ni0 = min(max(l0 - (K_ / 2), 0), L_ - K_);
    const int niL = min(max(l0 + TL - 1 - (K_ / 2), 0), L_ - K_);
    const int range = niL + K_ - ni0;   // <= 134

    // Vectorized staging: 4 halves (8B) per thread-iteration per tensor
    for (int i = tid; i < range * 8; i += TL) {
        int r = i >> 3, c = i & 7;
        size_t bs = ((size_t)(b * L_ + ni0 + r)) * (3 * C_) + h * D_ + c * 4;
        uint2 kk = *(const uint2*)(qkv + bs + C_);
        uint2 vv = *(const uint2*)(qkv + bs + 2 * C_);
        float2 k0 = __half22float2(*(__half2*)&kk.x);
        float2 k1 = __half22float2(*(__half2*)&kk.y);
        float2 v0 = __half22float2(*(__half2*)&vv.x);
        float2 v1 = __half22float2(*(__half2*)&vv.y);
        ks[r][c * 4 + 0] = k0.x; ks[r][c * 4 + 1] = k0.y;
        ks[r][c * 4 + 2] = k1.x; ks[r][c * 4 + 3] = k1.y;
        vs[r][c * 4 + 0] = v0.x; vs[r][c * 4 + 1] = v0.y;
        vs[r][c * 4 + 2] = v1.x; vs[r][c * 4 + 3] = v1.y;
    }
    __syncthreads();

    const int l = l0 + tid;
    const size_t mtok = (size_t)(b * L_ + l);
    const __half* qp = qkv + mtok * (3 * C_) + h * D_;

    float q[D_];
#pragma unroll
    for (int d2 = 0; d2 < D_ / 2; d2++) {
        float2 v = __half22float2(*(const __half2*)(qp + d2 * 2));
        q[d2 * 2 + 0] = v.x * SCALE_;
        q[d2 * 2 + 1] = v.y * SCALE_;
    }

    const int ni = min(max(l - (K_ / 2), 0), L_ - K_);
    float a[K_];
#pragma unroll
    for (int j = 0; j < K_; j++) {
        int r = ni + j - ni0;
        float dot = 0.f;
#pragma unroll
        for (int d = 0; d < D_; d++) dot += q[d] * ks[r][d];
        a[j] = dot + rpb[h * (2 * K_ - 1) + (ni + j - l + (K_ - 1))];
    }

    float m = a[0];
#pragma unroll
    for (int j = 1; j < K_; j++) m = fmaxf(m, a[j]);
    float s = 0.f;
#pragma unroll
    for (int j = 0; j < K_; j++) { a[j] = __expf(a[j] - m); s += a[j]; }
    float inv = 1.f / s;

    float o[D_];
#pragma unroll
    for (int d = 0; d < D_; d++) o[d] = 0.f;
#pragma unroll
    for (int j = 0; j < K_; j++) {
        float p = a[j] * inv;
        int r = ni + j - ni0;
#pragma unroll
        for (int d = 0; d < D_; d++) o[d] += p * vs[r][d];
    }

    // Write blocked swizzled fp16: kb = h, row = mtok
    const int sw = (int)((mtok >> 1) & 3);
    __half* dst = aob + ((size_t)h * MTOT + mtok) * 32;
#pragma unroll
    for (int c = 0; c < 4; c++) {
        __half2 h0 = __floats2half2_rn(o[c * 8 + 0], o[c * 8 + 1]);
        __half2 h1 = __floats2half2_rn(o[c * 8 + 2], o[c * 8 + 3]);
        __half2 h2 = __floats2half2_rn(o[c * 8 + 4], o[c * 8 + 5]);
        __half2 h3 = __floats2half2_rn(o[c * 8 + 6], o[c * 8 + 7]);
        uint4 u;
        u.x = *(unsigned*)&h0; u.y = *(unsigned*)&h1;
        u.z = *(unsigned*)&h2; u.w = *(unsigned*)&h3;
        *(uint4*)(dst + (c ^ sw) * 8) = u;
    }
}

// ---------------------------------------------------------------------------
extern "C" void kernel_launch(void* const* d_in, const int* in_sizes, int n_in,
                              void* d_out, int out_size)
{
    const float* x      = (const float*)d_in[0];
    const float* qkv_w  = (const float*)d_in[1];
    const float* qkv_b  = (const float*)d_in[2];
    const float* rpb    = (const float*)d_in[3];
    const float* proj_w = (const float*)d_in[4];
    const float* proj_b = (const float*)d_in[5];
    float* out = (float*)d_out;

    __half *xb, *w1b, *w2b, *qkv, *aob;
    cudaGetSymbolAddress((void**)&xb,  g_xb);
    cudaGetSymbolAddress((void**)&w1b, g_w1b);
    cudaGetSymbolAddress((void**)&w2b, g_w2b);
    cudaGetSymbolAddress((void**)&qkv, g_qkv);
    cudaGetSymbolAddress((void**)&aob, g_aob);

    cudaFuncSetAttribute(gemm_f16_blk<true>,
                         cudaFuncAttributeMaxDynamicSharedMemorySize, SMEM_REQ);
    cudaFuncSetAttribute(gemm_f16_blk<false>,
                         cudaFuncAttributeMaxDynamicSharedMemorySize, SMEM_REQ);

    // 0) Convert + block + swizzle GEMM operands
    {
        dim3 g1((MTOT * 4 + 255) / 256, C_ / 32);
        cvt_blocked_kernel<<<g1, 256>>>(x, xb, MTOT);
        dim3 g2((3 * C_ * 4 + 255) / 256, C_ / 32);
        cvt_blocked_kernel<<<g2, 256>>>(qkv_w, w1b, 3 * C_);
        dim3 g3((C_ * 4 + 255) / 256, C_ / 32);
        cvt_blocked_kernel<<<g3, 256>>>(proj_w, w2b, C_);
    }

    // 1) QKV = x @ qkv_w^T + qkv_b    (M x 1536, fp16 out)
    {
        dim3 grid((3 * C_) / GBN, MTOT / GBM);
        gemm_f16_blk<true><<<grid, 256, SMEM_REQ>>>(xb, w1b, qkv_b, qkv,
                                                    MTOT, 3 * C_);
    }

    // 2) Neighborhood attention -> aob (blocked fp16)
    {
        dim3 grid(L_ / TL, H_, B_);
        natt_kernel<<<grid, TL>>>(qkv, rpb, aob);
    }

    // 3) out = ao @ proj_w^T + proj_b (M x 512, fp32 out)
    {
        dim3 grid(C_ / GBN, MTOT / GBM);
        gemm_f16_blk<false><<<grid, 256, SMEM_REQ>>>(aob, w2b, proj_b, out,
                                                     MTOT, C_);
    }
}

// round 15
// speedup vs baseline: 1.0070x; 1.0070x over previous
#include <cuda_runtime.h>
#include <cuda_fp16.h>
#include <cstdint>

// Problem constants
#define B_  2
#define L_  16384
#define C_  512
#define H_  16
#define D_  32
#define K_  7
#define SCALE_ 0.17677669529663687f   // 32^-0.5
#define MTOT (B_ * L_)                // 32768

// Scratch (device globals). Blocked fp16 layout for GEMM operands:
//   buf[kb][row][32 halves], kb = k/32, with 16B-chunk swizzle c ^= (row>>1)&3
__device__ __half g_xb [(size_t)MTOT * C_];          // x, blocked
__device__ __half g_w1b[(size_t)3 * C_ * C_];        // qkv_w, blocked (rows = N)
__device__ __half g_w2b[(size_t)C_ * C_];            // proj_w, blocked
__device__ __half g_qkv[(size_t)MTOT * 3 * C_];      // qkv, plain row-major fp16
__device__ __half g_aob[(size_t)MTOT * C_];          // attention out, blocked

// ---------------------------------------------------------------------------
// f32 row-major [Mrows][512] -> blocked swizzled fp16 [kb][m][32]
// ---------------------------------------------------------------------------
__global__ void cvt_blocked_kernel(const float* __restrict__ in,
                                   __half* __restrict__ out, int Mrows)
{
    int t  = blockIdx.x * blockDim.x + threadIdx.x;
    int kb = blockIdx.y;
    int m  = t >> 2;
    int cd = t & 3;                       // stored chunk index
    if (m >= Mrows) return;
    int c = cd ^ ((m >> 1) & 3);          // logical chunk (involution)
    const float* src = in + (size_t)m * C_ + kb * 32 + c * 8;
    float4 v0 = *(const float4*)(src + 0);
    float4 v1 = *(const float4*)(src + 4);
    __half2 h0 = __floats2half2_rn(v0.x, v0.y);
    __half2 h1 = __floats2half2_rn(v0.z, v0.w);
    __half2 h2 = __floats2half2_rn(v1.x, v1.y);
    __half2 h3 = __floats2half2_rn(v1.z, v1.w);
    uint4 u;
    u.x = *(unsigned*)&h0; u.y = *(unsigned*)&h1;
    u.z = *(unsigned*)&h2; u.w = *(unsigned*)&h3;
    *(uint4*)(out + (((size_t)kb * Mrows + m) * 32 + cd * 8)) = u;
}

// ---------------------------------------------------------------------------
// FP16 tensor-core GEMM (f32 accum), bulk-async producer/consumer pipeline:
//   C[M,N] = A[M,K] @ W[N,K]^T + bias[N]
// Block 128x256, 256 threads (8 warps), warp tile 64x64, mma.m16n8k16,
// ldmatrix.x4, 6-slot bulk+mbarrier pipeline (3 slot-pairs), software-
// pipelined fragment double-buffering, NO CTA barriers in mainloop.
// Requires M%128==0, N%256==0, K==512.
// ---------------------------------------------------------------------------
#define GBM 128
#define GBN 256
#define GBK 32
#define A_BYT (GBM * 64)              // 8192
#define B_BYT (GBN * 64)              // 16384
#define STG   (A_BYT + B_BYT)         // 24576
#define NSTG  6
#define MBAR_OFF (NSTG * STG)         // 147456
#define EMPT_OFF (MBAR_OFF + NSTG * 8)
#define SMEM_REQ (EMPT_OFF + NSTG * 8)

__device__ __forceinline__ void mma16(float* d, const unsigned* a, const unsigned* b) {
    asm volatile(
        "mma.sync.aligned.m16n8k16.row.col.f32.f16.f16.f32 "
        "{%0,%1,%2,%3},{%4,%5,%6,%7},{%8,%9},{%0,%1,%2,%3};\n"
        : "+f"(d[0]), "+f"(d[1]), "+f"(d[2]), "+f"(d[3])
        : "r"(a[0]), "r"(a[1]), "r"(a[2]), "r"(a[3]), "r"(b[0]), "r"(b[1]));
}

__device__ __forceinline__ void ldsm4(unsigned* r, uint32_t addr) {
    asm volatile(
        "ldmatrix.sync.aligned.m8n8.x4.shared.b16 {%0,%1,%2,%3}, [%4];"
        : "=r"(r[0]), "=r"(r[1]), "=r"(r[2]), "=r"(r[3]) : "r"(addr));
}

__device__ __forceinline__ void mbar_init(uint32_t a, uint32_t cnt) {
    asm volatile("mbarrier.init.shared.b64 [%0], %1;" :: "r"(a), "r"(cnt) : "memory");
}
__device__ __forceinline__ void mbar_expect(uint32_t a, uint32_t tx) {
    asm volatile("mbarrier.arrive.expect_tx.shared.b64 _, [%0], %1;"
                 :: "r"(a), "r"(tx) : "memory");
}
__device__ __forceinline__ void mbar_arrive(uint32_t a) {
    asm volatile("mbarrier.arrive.shared.b64 _, [%0];" :: "r"(a) : "memory");
}
__device__ __forceinline__ void mbar_wait(uint32_t addr, uint32_t parity) {
    asm volatile(
        "{\n\t.reg .pred P;\n"
        "W%=:\n\t"
        "mbarrier.try_wait.parity.acquire.cta.shared::cta.b64 P, [%0], %1, 0x989680;\n\t"
        "@P bra D%=;\n\t"
        "bra W%=;\n"
        "D%=:\n\t}"
        :: "r"(addr), "r"(parity) : "memory");
}
__device__ __forceinline__ void bulk_g2s(uint32_t dst, const void* src,
                                         uint32_t bytes, uint32_t mbar) {
    asm volatile(
        "cp.async.bulk.shared::cta.global.mbarrier::complete_tx::bytes "
        "[%0], [%1], %2, [%3];"
        :: "r"(dst), "l"(src), "r"(bytes), "r"(mbar) : "memory");
}

struct Frag { unsigned a[4][4]; unsigned b[8][2]; };

template<bool HOUT>
__global__ __launch_bounds__(256, 1) void gemm_f16_blk(
    const __half* __restrict__ Ab, const __half* __restrict__ Wb,
    const float* __restrict__ bias, void* __restrict__ Co,
    int M, int N)
{
    extern __shared__ char smem_raw[];
    uint32_t base;
    asm("{ .reg .u64 t; cvta.to.shared.u64 t, %1; cvt.u32.u64 %0, t; }"
        : "=r"(base) : "l"(smem_raw));

    const int tid  = threadIdx.x;
    const int lane = tid & 31;
    const int warp = tid >> 5;
    const int bm = blockIdx.y * GBM;
    const int bn = blockIdx.x * GBN;
    const int wm0 = (warp >> 2) * 64;   // 0 or 64
    const int wn0 = (warp & 3) * 64;    // 0,64,128,192
    const int NP = (C_ / GBK) / 2;      // 8 pair-rounds

    const uint32_t mbf = base + MBAR_OFF;   // full barriers
    const uint32_t mbe = base + EMPT_OFF;   // empty barriers

    if (tid == 0) {
#pragma unroll
        for (int s = 0; s < NSTG; s++) {
            mbar_init(mbf + s * 8, 1);
            mbar_init(mbe + s * 8, 8);      // one arrive per warp
        }
    }
    __syncthreads();   // only CTA barrier: mbarrier init visibility

    // Issue tile kt into slot
    auto issue = [&](int kt, int slot) {
        uint32_t bar = mbf + slot * 8;
        mbar_expect(bar, STG);
        const char* srcA = (const char*)Ab + ((size_t)kt * M + bm) * 64;
        const char* srcB = (const char*)Wb + ((size_t)kt * N + bn) * 64;
        bulk_g2s(base + slot * STG,          srcA, A_BYT, bar);
        bulk_g2s(base + slot * STG + A_BYT,  srcB, B_BYT, bar);
    };

    // Prologue: pairs 0 and 1 (tiles 0..3)
    if (tid == 0) {
        issue(0, 0); issue(1, 1);
        issue(2, 2); issue(3, 3);
    }

    float acc[4][8][4];
#pragma unroll
    for (int i = 0; i < 4; i++)
#pragma unroll
        for (int j = 0; j < 8; j++)
#pragma unroll
            for (int c = 0; c < 4; c++) acc[i][j][c] = 0.f;

    // ldmatrix lane addressing
    const int a_row = (lane & 15);
    const int a_c1  = (lane >> 4);
    const int b_row = (lane & 7) + ((lane >> 4) & 1) * 8;
    const int b_c1  = ((lane >> 3) & 1);

    auto load_frags = [&](Frag& f, uint32_t sa, int ks) {
        const uint32_t sb = sa + A_BYT;
#pragma unroll
        for (int mt = 0; mt < 4; mt++) {
            int row = wm0 + mt * 16 + a_row;
            int c = (ks * 2 + a_c1) ^ ((row >> 1) & 3);
            ldsm4(f.a[mt], sa + row * 64 + c * 16);
        }
#pragma unroll
        for (int p = 0; p < 4; p++) {
            unsigned t[4];
            int row = wn0 + p * 16 + b_row;
            int c = (ks * 2 + b_c1) ^ ((row >> 1) & 3);
            ldsm4(t, sb + row * 64 + c * 16);
            f.b[2 * p + 0][0] = t[0]; f.b[2 * p + 0][1] = t[1];
            f.b[2 * p + 1][0] = t[2]; f.b[2 * p + 1][1] = t[3];
        }
    };
    auto mma_all = [&](Frag& f) {
#pragma unroll
        for (int mt = 0; mt < 4; mt++)
#pragma unroll
            for (int nt = 0; nt < 8; nt++)
                mma16(acc[mt][nt], f.a[mt], f.b[nt]);
    };

    Frag F0, F1;

    for (int kp = 0; kp < NP; kp++) {
        const int s0 = (kp % 3) * 2;
        const uint32_t par = (kp / 3) & 1;
        mbar_wait(mbf + s0 * 8, par);
        mbar_wait(mbf + (s0 + 1) * 8, par);

        // Producer: issue pair kp+2 once its slot-pair is empty.
        if (tid == 0 && kp + 2 < NP) {
            const int np = kp + 2;
            const int ns = (np % 3) * 2;
            const uint32_t epar = 1u ^ ((uint32_t)(np / 3) & 1u);
            mbar_wait(mbe + ns * 8, epar);
            mbar_wait(mbe + (ns + 1) * 8, epar);
            issue(2 * np, ns);
            issue(2 * np + 1, ns + 1);
        }

        const uint32_t sa0 = base + s0 * STG;
        const uint32_t sa1 = sa0 + STG;

        // Software-pipelined: ldsm(step+1) overlaps mma(step)
        load_frags(F0, sa0, 0);
        load_frags(F1, sa0, 1);  mma_all(F0);
        load_frags(F0, sa1, 0);  mma_all(F1);
        load_frags(F1, sa1, 1);  mma_all(F0);
        mma_all(F1);

        if (lane == 0) {
            mbar_arrive(mbe + s0 * 8);
            mbar_arrive(mbe + (s0 + 1) * 8);
        }
    }

    // Epilogue: bias + store
    const int g  = lane >> 2;
    const int tq = lane & 3;
#pragma unroll
    for (int nt = 0; nt < 8; nt++) {
        int col = bn + wn0 + nt * 8 + tq * 2;
        float2 bb = *(const float2*)&bias[col];
#pragma unroll
        for (int mt = 0; mt < 4; mt++) {
            int row = bm + wm0 + mt * 16 + g;
            if (HOUT) {
                __half* cp = (__half*)Co;
                __half2 v0 = __floats2half2_rn(acc[mt][nt][0] + bb.x,
                                               acc[mt][nt][1] + bb.y);
                __half2 v1 = __floats2half2_rn(acc[mt][nt][2] + bb.x,
                                               acc[mt][nt][3] + bb.y);
                *(__half2*)(cp + (size_t)row * N + col) = v0;
                *(__half2*)(cp + (size_t)(row + 8) * N + col) = v1;
            } else {
                float* cp = (float*)Co;
                float2 o0, o1;
                o0.x = acc[mt][nt][0] + bb.x; o0.y = acc[mt][nt][1] + bb.y;
                o1.x = acc[mt][nt][2] + bb.x; o1.y = acc[mt][nt][3] + bb.y;
                *(float2*)(cp + (size_t)row * N + col) = o0;
                *(float2*)(cp + (size_t)(row + 8) * N + col) = o1;
            }
        }
    }
}

// ---------------------------------------------------------------------------
// Neighborhood attention, K=7, D=32. fp16 qkv in; blocked fp16 ao out.
// ---------------------------------------------------------------------------
#define TL 128

__global__ __launch_bounds__(128) void natt_kernel(
    const __half* __restrict__ qkv, const float* __restrict__ rpb,
    __half* __restrict__ aob)
{
    __shared__ float ks[134][33];
    __shared__ float vs[134][33];

    const int b  = blockIdx.z;
    const int h  = blockIdx.y;
    const int l0 = blockIdx.x * TL;
    const int tid = threadIdx.x;

    const int ni0 = min(max(l0 - (K_ / 2), 0), L_ - K_);
    const int niL = min(max(l0 + TL - 1 - (K_ / 2), 0), L_ - K_);
    const int range = niL + K_ - ni0;   // <= 134

    // Vectorized staging: 4 halves (8B) per thread-iteration per tensor
    for (int i = tid; i < range * 8; i += TL) {
        int r = i >> 3, c = i & 7;
        size_t bs = ((size_t)(b * L_ + ni0 + r)) * (3 * C_) + h * D_ + c * 4;
        uint2 kk = *(const uint2*)(qkv + bs + C_);
        uint2 vv = *(const uint2*)(qkv + bs + 2 * C_);
        float2 k0 = __half22float2(*(__half2*)&kk.x);
        float2 k1 = __half22float2(*(__half2*)&kk.y);
        float2 v0 = __half22float2(*(__half2*)&vv.x);
        float2 v1 = __half22float2(*(__half2*)&vv.y);
        ks[r][c * 4 + 0] = k0.x; ks[r][c * 4 + 1] = k0.y;
        ks[r][c * 4 + 2] = k1.x; ks[r][c * 4 + 3] = k1.y;
        vs[r][c * 4 + 0] = v0.x; vs[r][c * 4 + 1] = v0.y;
        vs[r][c * 4 + 2] = v1.x; vs[r][c * 4 + 3] = v1.y;
    }
    __syncthreads();

    const int l = l0 + tid;
    const size_t mtok = (size_t)(b * L_ + l);
    const __half* qp = qkv + mtok * (3 * C_) + h * D_;

    float q[D_];
#pragma unroll
    for (int d2 = 0; d2 < D_ / 2; d2++) {
        float2 v = __half22float2(*(const __half2*)(qp + d2 * 2));
        q[d2 * 2 + 0] = v.x * SCALE_;
        q[d2 * 2 + 1] = v.y * SCALE_;
    }

    const int ni = min(max(l - (K_ / 2), 0), L_ - K_);
    float a[K_];
#pragma unroll
    for (int j = 0; j < K_; j++) {
        int r = ni + j - ni0;
        float dot = 0.f;
#pragma unroll
        for (int d = 0; d < D_; d++) dot += q[d] * ks[r][d];
        a[j] = dot + rpb[h * (2 * K_ - 1) + (ni + j - l + (K_ - 1))];
    }

    float m = a[0];
#pragma unroll
    for (int j = 1; j < K_; j++) m = fmaxf(m, a[j]);
    float s = 0.f;
#pragma unroll
    for (int j = 0; j < K_; j++) { a[j] = __expf(a[j] - m); s += a[j]; }
    float inv = 1.f / s;

    float o[D_];
#pragma unroll
    for (int d = 0; d < D_; d++) o[d] = 0.f;
#pragma unroll
    for (int j = 0; j < K_; j++) {
        float p = a[j] * inv;
        int r = ni + j - ni0;
#pragma unroll
        for (int d = 0; d < D_; d++) o[d] += p * vs[r][d];
    }

    // Write blocked swizzled fp16: kb = h, row = mtok
    const int sw = (int)((mtok >> 1) & 3);
    __half* dst = aob + ((size_t)h * MTOT + mtok) * 32;
#pragma unroll
    for (int c = 0; c < 4; c++) {
        __half2 h0 = __floats2half2_rn(o[c * 8 + 0], o[c * 8 + 1]);
        __half2 h1 = __floats2half2_rn(o[c * 8 + 2], o[c * 8 + 3]);
        __half2 h2 = __floats2half2_rn(o[c * 8 + 4], o[c * 8 + 5]);
        __half2 h3 = __floats2half2_rn(o[c * 8 + 6], o[c * 8 + 7]);
        uint4 u;
        u.x = *(unsigned*)&h0; u.y = *(unsigned*)&h1;
        u.z = *(unsigned*)&h2; u.w = *(unsigned*)&h3;
        *(uint4*)(dst + (c ^ sw) * 8) = u;
    }
}

// ---------------------------------------------------------------------------
extern "C" void kernel_launch(void* const* d_in, const int* in_sizes, int n_in,
                              void* d_out, int out_size)
{
    const float* x      = (const float*)d_in[0];
    const float* qkv_w  = (const float*)d_in[1];
    const float* qkv_b  = (const float*)d_in[2];
    const float* rpb    = (const float*)d_in[3];
    const float* proj_w = (const float*)d_in[4];
    const float* proj_b = (const float*)d_in[5];
    float* out = (float*)d_out;

    __half *xb, *w1b, *w2b, *qkv, *aob;
    cudaGetSymbolAddress((void**)&xb,  g_xb);
    cudaGetSymbolAddress((void**)&w1b, g_w1b);
    cudaGetSymbolAddress((void**)&w2b, g_w2b);
    cudaGetSymbolAddress((void**)&qkv, g_qkv);
    cudaGetSymbolAddress((void**)&aob, g_aob);

    cudaFuncSetAttribute(gemm_f16_blk<true>,
                         cudaFuncAttributeMaxDynamicSharedMemorySize, SMEM_REQ);
    cudaFuncSetAttribute(gemm_f16_blk<false>,
                         cudaFuncAttributeMaxDynamicSharedMemorySize, SMEM_REQ);

    // 0) Convert + block + swizzle GEMM operands
    {
        dim3 g1((MTOT * 4 + 255) / 256, C_ / 32);
        cvt_blocked_kernel<<<g1, 256>>>(x, xb, MTOT);
        dim3 g2((3 * C_ * 4 + 255) / 256, C_ / 32);
        cvt_blocked_kernel<<<g2, 256>>>(qkv_w, w1b, 3 * C_);
        dim3 g3((C_ * 4 + 255) / 256, C_ / 32);
        cvt_blocked_kernel<<<g3, 256>>>(proj_w, w2b, C_);
    }

    // 1) QKV = x @ qkv_w^T + qkv_b    (M x 1536, fp16 out)
    {
        dim3 grid((3 * C_) / GBN, MTOT / GBM);
        gemm_f16_blk<true><<<grid, 256, SMEM_REQ>>>(xb, w1b, qkv_b, qkv,
                                                    MTOT, 3 * C_);
    }

    // 2) Neighborhood attention -> aob (blocked fp16)
    {
        dim3 grid(L_ / TL, H_, B_);
        natt_kernel<<<grid, TL>>>(qkv, rpb, aob);
    }

    // 3) out = ao @ proj_w^T + proj_b (M x 512, fp32 out)
    {
        dim3 grid(C_ / GBN, MTOT / GBM);
        gemm_f16_blk<false><<<grid, 256, SMEM_REQ>>>(aob, w2b, proj_b, out,
                                                     MTOT, C_);
    }
}